// round 13
// baseline (speedup 1.0000x reference)
#include <cuda_runtime.h>
#include <math.h>
#include <stdint.h>

// ---------------------------------------------------------------------------
// DeepseekV4LearnedRouter — fused 1-pass TF32 GEMM (BM=64 x BN=256, routing in
// epilogue) + targeted bit-exact refinement.
//   Each CTA computes full 256-expert logits for 64 tokens, routes them
//   in-kernel (top-8 + flagging), writes probs/rmap/logits. Flagged tokens
//   (8th/9th biased gap < TAU) are re-scored exactly by refine_kernel.
// ---------------------------------------------------------------------------

#define BM 64
#define BN 256
#define KC 32
#define SA 36                            // smem row stride (f32)
#define TILE_A_WORDS (64 * SA)           // 2304
#define TILE_B_WORDS (256 * SA)          // 9216
#define STAGE_WORDS (TILE_A_WORDS + TILE_B_WORDS)   // 11520
#define BIAS_OFF (2 * STAGE_WORDS)       // word offset of bias array
#define SMEM_BYTES ((2 * STAGE_WORDS + 256) * 4)    // 93184 -> 2 CTAs/SM
#define LGS 260                          // epilogue logits smem stride (words)

#define MAX_N 16384
#define MAX_E 256
#define TAU 2e-3f

#define RCK 1024                         // refine chunk (k per stage)
#define RNC 2                            // refine candidates per pass
#define RPAD 8

__device__ float g_logits[(size_t)MAX_N * MAX_E];
__device__ int   g_flag_count;
__device__ int   g_flag_list[MAX_N];

__device__ __forceinline__ uint32_t smem_u32(const void* p) {
    uint32_t a;
    asm("{ .reg .u64 t; cvta.to.shared.u64 t, %1; cvt.u32.u64 %0, t; }" : "=r"(a) : "l"(p));
    return a;
}
__device__ __forceinline__ uint32_t f2tf32(float x) {
    uint32_t r;
    asm("cvt.rna.tf32.f32 %0, %1;" : "=r"(r) : "f"(x));
    return r;
}
__device__ __forceinline__ void cp_async16(uint32_t saddr, const void* g) {
    asm volatile("cp.async.cg.shared.global [%0], [%1], 16;" :: "r"(saddr), "l"(g));
}
__device__ __forceinline__ void cp_commit() {
    asm volatile("cp.async.commit_group;" ::: "memory");
}
template <int N>
__device__ __forceinline__ void cp_wait() {
    asm volatile("cp.async.wait_group %0;" :: "n"(N) : "memory");
}
__device__ __forceinline__ void mma_tf32(float* d, const uint32_t* a, const uint32_t* b) {
    asm volatile(
        "mma.sync.aligned.m16n8k8.row.col.f32.tf32.tf32.f32 "
        "{%0,%1,%2,%3}, {%4,%5,%6,%7}, {%8,%9}, {%0,%1,%2,%3};"
        : "+f"(d[0]), "+f"(d[1]), "+f"(d[2]), "+f"(d[3])
        : "r"(a[0]), "r"(a[1]), "r"(a[2]), "r"(a[3]), "r"(b[0]), "r"(b[1]));
}
__device__ __forceinline__ void warp_argmax(float& bestv, int& beste) {
#pragma unroll
    for (int off = 16; off > 0; off >>= 1) {
        const float ov = __shfl_xor_sync(0xffffffffu, bestv, off);
        const int   oe = __shfl_xor_sync(0xffffffffu, beste, off);
        if (ov > bestv || (ov == bestv && oe < beste)) { bestv = ov; beste = oe; }
    }
}

// ---------------- fused GEMM + routing --------------------------------------
__global__ __launch_bounds__(256, 2)
void gemm_route_kernel(const float* __restrict__ A,     // [N, K] hidden
                       const float* __restrict__ W,     // [E, K] weight
                       const float* __restrict__ bias,  // [E]
                       float* __restrict__ C,           // [N, E] logits
                       float* __restrict__ probs,
                       float* __restrict__ rmap,
                       int K)
{
    extern __shared__ float sm[];
    const uint32_t sbase = smem_u32(sm);

    const int tid  = threadIdx.x;
    const int lane = tid & 31;
    const int w    = tid >> 5;        // 0..7
    const int wm   = w & 1;           // m offset 32*wm
    const int wn   = w >> 1;          // n offset 64*wn
    const int g    = lane >> 2;       // 0..7
    const int t    = lane & 3;        // 0..3

    const int mBase = blockIdx.x * BM;
    const int KT    = K / KC;         // 128

    const float* Ag = A + (size_t)mBase * K;

    // bias -> smem (persists above stage buffers)
    sm[BIAS_OFF + tid] = bias[tid];

    auto load_stage = [&](int stage, int k0) {
        const uint32_t sA = sbase + (uint32_t)stage * STAGE_WORDS * 4;
        const uint32_t sW = sA + TILE_A_WORDS * 4;
#pragma unroll
        for (int i = 0; i < 2; i++) {           // 512 float4 of A
            const int c   = tid + i * 256;
            const int row = c >> 3;
            const int c8  = c & 7;
            cp_async16(sA + (uint32_t)(row * SA + c8 * 4) * 4,
                       Ag + (size_t)row * K + k0 + c8 * 4);
        }
#pragma unroll
        for (int i = 0; i < 8; i++) {           // 2048 float4 of W
            const int c   = tid + i * 256;
            const int row = c >> 3;
            const int c8  = c & 7;
            cp_async16(sW + (uint32_t)(row * SA + c8 * 4) * 4,
                       W + (size_t)row * K + k0 + c8 * 4);
        }
        cp_commit();
    };

    float acc[2][8][4];
#pragma unroll
    for (int mt = 0; mt < 2; mt++)
#pragma unroll
        for (int nt = 0; nt < 8; nt++)
#pragma unroll
            for (int i = 0; i < 4; i++)
                acc[mt][nt][i] = 0.0f;

    load_stage(0, 0);
    load_stage(1, KC);

    for (int kt = 0; kt < KT; ++kt) {
        cp_wait<1>();
        __syncthreads();

        const float* Asm = sm + (kt & 1) * STAGE_WORDS;
        const float* Wsm = Asm + TILE_A_WORDS;
        const float* ap = Asm + (wm * 32 + g) * SA;
        const float* bp = Wsm + (wn * 64 + g) * SA;

#pragma unroll
        for (int ks = 0; ks < KC / 8; ks++) {
            const int k0 = ks * 8 + t;

            uint32_t Bh[16];
#pragma unroll
            for (int nt = 0; nt < 8; nt++) {
                Bh[nt * 2]     = f2tf32(bp[nt * 8 * SA + k0]);
                Bh[nt * 2 + 1] = f2tf32(bp[nt * 8 * SA + k0 + 4]);
            }
            uint32_t Ah[8];
#pragma unroll
            for (int mt = 0; mt < 2; mt++) {
                Ah[mt * 4 + 0] = f2tf32(ap[mt * 16 * SA + k0]);
                Ah[mt * 4 + 1] = f2tf32(ap[mt * 16 * SA + 8 * SA + k0]);
                Ah[mt * 4 + 2] = f2tf32(ap[mt * 16 * SA + k0 + 4]);
                Ah[mt * 4 + 3] = f2tf32(ap[mt * 16 * SA + 8 * SA + k0 + 4]);
            }

#pragma unroll
            for (int mt = 0; mt < 2; mt++)
#pragma unroll
                for (int nt = 0; nt < 8; nt++)
                    mma_tf32(acc[mt][nt], &Ah[mt * 4], &Bh[nt * 2]);
        }

        __syncthreads();
        if (kt + 2 < KT) load_stage(kt & 1, (kt + 2) * KC);
        else cp_commit();   // keep group count uniform for cp_wait<1>
    }

    // ---- epilogue: accs -> smem logits tile (reuse stage bufs) + gmem ------
    __syncthreads();   // all consumers done with stage buffers
    float* lg = sm;    // [64][LGS]
#pragma unroll
    for (int mt = 0; mt < 2; mt++) {
        const int r0 = wm * 32 + mt * 16 + g;
#pragma unroll
        for (int nt = 0; nt < 8; nt++) {
            const int col = wn * 64 + nt * 8 + 2 * t;
            lg[r0 * LGS + col]           = acc[mt][nt][0];
            lg[r0 * LGS + col + 1]       = acc[mt][nt][1];
            lg[(r0 + 8) * LGS + col]     = acc[mt][nt][2];
            lg[(r0 + 8) * LGS + col + 1] = acc[mt][nt][3];
            float2* p0 = (float2*)(C + (size_t)(mBase + r0) * 256 + col);
            float2* p1 = (float2*)(C + (size_t)(mBase + r0 + 8) * 256 + col);
            *p0 = make_float2(acc[mt][nt][0], acc[mt][nt][1]);
            *p1 = make_float2(acc[mt][nt][2], acc[mt][nt][3]);
        }
    }
    __syncthreads();

    // ---- routing: 8 warps x 8 tokens ---------------------------------------
    const float* bias_sm = sm + BIAS_OFF;
    float biasv[8];
#pragma unroll
    for (int j = 0; j < 8; j++) biasv[j] = bias_sm[j * 32 + lane];

    for (int ti = 0; ti < 8; ++ti) {
        const int tok = w * 8 + ti;
        const float* lrow = lg + tok * LGS;

        float score[8], selsc[8];
        bool  sel[8];
#pragma unroll
        for (int j = 0; j < 8; j++) {
            const float x = lrow[j * 32 + lane];
            const float sp = fmaxf(x, 0.0f) + log1pf(expf(-fabsf(x)));
            score[j] = sqrtf(sp);
            selsc[j] = score[j] + biasv[j];
            sel[j] = false;
        }

        float sumw = 0.0f, v8 = 0.0f, v9 = 0.0f;
#pragma unroll
        for (int it = 0; it < 9; it++) {
            float bestv = -INFINITY;
            int bestj = -1;
#pragma unroll
            for (int j = 0; j < 8; j++)
                if (selsc[j] > bestv) { bestv = selsc[j]; bestj = j; }
            int beste = (bestj >= 0) ? (bestj * 32 + lane) : 0x7fffffff;
            warp_argmax(bestv, beste);
            if (it == 7) v8 = bestv;
            if (it == 8) { v9 = bestv; break; }
            if ((beste & 31) == lane) {
                const int j = beste >> 5;
                sel[j] = true;
                selsc[j] = -INFINITY;
                sumw += score[j];
            }
        }

        float tot = sumw;
#pragma unroll
        for (int off = 16; off > 0; off >>= 1)
            tot += __shfl_xor_sync(0xffffffffu, tot, off);
        const float scale = 2.5f / fmaxf(tot, 1e-12f);

        const size_t orow = (size_t)(mBase + tok) * 256;
#pragma unroll
        for (int j = 0; j < 8; j++) {
            const int e = j * 32 + lane;
            probs[orow + e] = sel[j] ? score[j] * scale : 0.0f;
            rmap[orow + e]  = sel[j] ? 1.0f : 0.0f;
        }

        if (lane == 0 && (v8 - v9) < TAU) {
            const int idx = atomicAdd(&g_flag_count, 1);
            g_flag_list[idx] = mBase + tok;
        }
    }
}

// ---------------- targeted exact refinement (one block / flagged token) -----
__global__ __launch_bounds__(128)
void refine_kernel(const float* __restrict__ A,
                   const float* __restrict__ W,
                   const float* __restrict__ bias,
                   const float* __restrict__ logits,
                   float* __restrict__ probs,
                   float* __restrict__ rmap,
                   int K)
{
    __shared__ float hsm[4096];
    __shared__ float wbuf[2][RNC][RCK + RPAD];
    __shared__ float exsc[32];
    __shared__ int   exid[32];
    __shared__ int   ncs;

    const int tid  = threadIdx.x;
    const int wid  = tid >> 5;
    const int lane = tid & 31;
    const int cnt  = g_flag_count;
    const int NCH  = K / RCK;          // 4

    for (int i = blockIdx.x; i < cnt; i += gridDim.x) {
        const int tk = g_flag_list[i];

        const float4* hsrc = (const float4*)(A + (size_t)tk * K);
        for (int j = tid; j < K / 4; j += 128)
            ((float4*)hsm)[j] = hsrc[j];

        float score[8], selsc[8], biasv[8];
        if (wid == 0) {
            const float* lrow = logits + (size_t)tk * 256;
#pragma unroll
            for (int j = 0; j < 8; j++) {
                const int e = j * 32 + lane;
                const float x = lrow[e];
                const float sp = fmaxf(x, 0.0f) + log1pf(expf(-fabsf(x)));
                score[j] = sqrtf(sp);
                biasv[j] = bias[e];
                selsc[j] = score[j] + biasv[j];
            }
            float tmp[8];
#pragma unroll
            for (int j = 0; j < 8; j++) tmp[j] = selsc[j];
            float v8 = -INFINITY;
#pragma unroll
            for (int it = 0; it < 8; it++) {
                float bestv = -INFINITY;
                int bestj = -1;
#pragma unroll
                for (int j = 0; j < 8; j++)
                    if (tmp[j] > bestv) { bestv = tmp[j]; bestj = j; }
                int beste = (bestj >= 0) ? (bestj * 32 + lane) : 0x7fffffff;
                warp_argmax(bestv, beste);
                if (it == 7) v8 = bestv;
                if ((beste & 31) == lane) tmp[beste >> 5] = -INFINITY;
            }
            if (lane == 0) ncs = 0;
            __syncwarp();
#pragma unroll
            for (int j = 0; j < 8; j++) {
                if (fabsf(selsc[j] - v8) <= TAU) {
                    const int slot = atomicAdd(&ncs, 1);
                    if (slot < 32) exid[slot] = j * 32 + lane;
                }
            }
        }
        __syncthreads();
        const int nc = min(ncs, 32);

        for (int c0 = 0; c0 < nc; c0 += RNC) {
            const int gnc = min(RNC, nc - c0);

            for (int idx = tid; idx < gnc * (RCK / 4); idx += 128) {
                const int cand = idx / (RCK / 4);
                const int f4   = idx % (RCK / 4);
                const int e    = exid[c0 + cand];
                *(float4*)&wbuf[0][cand][f4 * 4] =
                    *(const float4*)(W + (size_t)e * K + f4 * 4);
            }
            __syncthreads();

            float acc = 0.0f;
            for (int ch = 0; ch < NCH; ch++) {
                const int cur = ch & 1;
                if (wid > 0) {
                    if (ch + 1 < NCH) {
                        const int tj = tid - 32;
                        for (int idx = tj; idx < gnc * (RCK / 4); idx += 96) {
                            const int cand = idx / (RCK / 4);
                            const int f4   = idx % (RCK / 4);
                            const int e    = exid[c0 + cand];
                            *(float4*)&wbuf[cur ^ 1][cand][f4 * 4] =
                                *(const float4*)(W + (size_t)e * K + (ch + 1) * RCK + f4 * 4);
                        }
                    }
                } else if (lane < gnc) {
                    // bit-exact ascending-k single-accumulator fmaf chain
                    const float* wv = wbuf[cur][lane];
                    const float* hv = hsm + ch * RCK;
#pragma unroll 8
                    for (int k = 0; k < RCK; k += 4) {
                        acc = fmaf(hv[k],     wv[k],     acc);
                        acc = fmaf(hv[k + 1], wv[k + 1], acc);
                        acc = fmaf(hv[k + 2], wv[k + 2], acc);
                        acc = fmaf(hv[k + 3], wv[k + 3], acc);
                    }
                }
                __syncthreads();
            }
            if (wid == 0 && lane < gnc) {
                const float sp = fmaxf(acc, 0.0f) + log1pf(expf(-fabsf(acc)));
                exsc[c0 + lane] = sqrtf(sp);
            }
            __syncthreads();
        }

        if (wid == 0) {
            for (int c = 0; c < nc; c++) {
                const int e = exid[c];
                if ((e & 31) == lane) {
                    const int j = e >> 5;
                    score[j] = exsc[c];
                    selsc[j] = score[j] + biasv[j];
                }
            }
            bool sel[8];
#pragma unroll
            for (int j = 0; j < 8; j++) sel[j] = false;
            float sumw = 0.0f;
#pragma unroll
            for (int it = 0; it < 8; it++) {
                float bestv = -INFINITY;
                int bestj = -1;
#pragma unroll
                for (int j = 0; j < 8; j++)
                    if (selsc[j] > bestv) { bestv = selsc[j]; bestj = j; }
                int beste = (bestj >= 0) ? (bestj * 32 + lane) : 0x7fffffff;
                warp_argmax(bestv, beste);
                if ((beste & 31) == lane) {
                    const int j = beste >> 5;
                    sel[j] = true;
                    selsc[j] = -INFINITY;
                    sumw += score[j];
                }
            }
            float tot = sumw;
#pragma unroll
            for (int off = 16; off > 0; off >>= 1)
                tot += __shfl_xor_sync(0xffffffffu, tot, off);
            const float scale = 2.5f / fmaxf(tot, 1e-12f);

#pragma unroll
            for (int j = 0; j < 8; j++) {
                const int e = j * 32 + lane;
                const size_t o = (size_t)tk * 256 + e;
                probs[o] = sel[j] ? score[j] * scale : 0.0f;
                rmap[o]  = sel[j] ? 1.0f : 0.0f;
            }
        }
        __syncthreads();
    }
}

extern "C" void kernel_launch(void* const* d_in, const int* in_sizes, int n_in,
                              void* d_out, int out_size)
{
    const float* hidden = (const float*)d_in[0];
    const float* weight = (const float*)d_in[1];
    const float* bias   = (const float*)d_in[2];

    const int E = in_sizes[2];
    const int D = in_sizes[1] / E;
    const int N = in_sizes[0] / D;

    float* out   = (float*)d_out;
    float* probs = out;
    float* rmap  = out + (size_t)N * E;

    float* logits = nullptr;
    cudaGetSymbolAddress((void**)&logits, g_logits);
    void* fc = nullptr;
    cudaGetSymbolAddress(&fc, g_flag_count);

    cudaMemsetAsync(fc, 0, sizeof(int));

    cudaFuncSetAttribute(gemm_route_kernel,
                         cudaFuncAttributeMaxDynamicSharedMemorySize, SMEM_BYTES);

    gemm_route_kernel<<<N / BM, 256, SMEM_BYTES>>>(hidden, weight, bias, logits,
                                                   probs, rmap, D);

    refine_kernel<<<1024, 128>>>(hidden, weight, bias, logits, probs, rmap, D);

    (void)n_in; (void)out_size;
}

// round 14
// speedup vs baseline: 1.1825x; 1.1825x over previous
#include <cuda_runtime.h>
#include <math.h>
#include <stdint.h>

// ---------------------------------------------------------------------------
// DeepseekV4LearnedRouter — 1-pass TF32 mma.sync GEMM (round-9 validated
// config) + vectorized top-8 + targeted bit-exact refinement (wider grid).
// ---------------------------------------------------------------------------

#define BM 128
#define BN 128
#define KC 32
#define SA 36                         // smem row stride (f32); conflict-free frags
#define TILE_WORDS (128 * SA)         // 4608
#define STAGE_WORDS (2 * TILE_WORDS)  // 9216
#define SMEM_BYTES (2 * STAGE_WORDS * 4)   // 73728

#define MAX_N 16384
#define MAX_E 256
#define TAU 2e-3f

#define RCK 1024                      // refine chunk (k per stage)
#define RNC 2                         // refine candidates per pass
#define RPAD 8

__device__ float g_logits[(size_t)MAX_N * MAX_E];
__device__ int   g_flag_count;
__device__ int   g_flag_list[MAX_N];

__device__ __forceinline__ uint32_t smem_u32(const void* p) {
    uint32_t a;
    asm("{ .reg .u64 t; cvta.to.shared.u64 t, %1; cvt.u32.u64 %0, t; }" : "=r"(a) : "l"(p));
    return a;
}
__device__ __forceinline__ uint32_t f2tf32(float x) {
    uint32_t r;
    asm("cvt.rna.tf32.f32 %0, %1;" : "=r"(r) : "f"(x));
    return r;
}
__device__ __forceinline__ void cp_async16(uint32_t saddr, const void* g) {
    asm volatile("cp.async.cg.shared.global [%0], [%1], 16;" :: "r"(saddr), "l"(g));
}
__device__ __forceinline__ void cp_commit() {
    asm volatile("cp.async.commit_group;" ::: "memory");
}
template <int N>
__device__ __forceinline__ void cp_wait() {
    asm volatile("cp.async.wait_group %0;" :: "n"(N) : "memory");
}
__device__ __forceinline__ void mma_tf32(float* d, const uint32_t* a, const uint32_t* b) {
    asm volatile(
        "mma.sync.aligned.m16n8k8.row.col.f32.tf32.tf32.f32 "
        "{%0,%1,%2,%3}, {%4,%5,%6,%7}, {%8,%9}, {%0,%1,%2,%3};"
        : "+f"(d[0]), "+f"(d[1]), "+f"(d[2]), "+f"(d[3])
        : "r"(a[0]), "r"(a[1]), "r"(a[2]), "r"(a[3]), "r"(b[0]), "r"(b[1]));
}
__device__ __forceinline__ void warp_argmax(float& bestv, int& beste) {
#pragma unroll
    for (int off = 16; off > 0; off >>= 1) {
        const float ov = __shfl_xor_sync(0xffffffffu, bestv, off);
        const int   oe = __shfl_xor_sync(0xffffffffu, beste, off);
        if (ov > bestv || (ov == bestv && oe < beste)) { bestv = ov; beste = oe; }
    }
}

// ---------------- GEMM: logits = A @ W^T (1-pass TF32, 64x64 warp tiles) ----
__global__ __launch_bounds__(128, 2)
void gemm_tf32_kernel(const float* __restrict__ A,
                      const float* __restrict__ W,
                      float* __restrict__ C,
                      int E, int K)
{
    extern __shared__ float sm[];
    const uint32_t sbase = smem_u32(sm);

    const int tid  = threadIdx.x;
    const int lane = tid & 31;
    const int w    = tid >> 5;         // 0..3
    const int wm   = w & 1;            // m offset 64*wm
    const int wn   = w >> 1;           // n offset 64*wn
    const int g    = lane >> 2;        // 0..7
    const int t    = lane & 3;         // 0..3

    const int nBase = blockIdx.x * BN;
    const int mBase = blockIdx.y * BM;
    const int KT    = K / KC;          // 128

    const float* Ag = A + (size_t)mBase * K;
    const float* Wg = W + (size_t)nBase * K;

    auto load_stage = [&](int stage, int k0) {
        const uint32_t sA = sbase + (uint32_t)stage * STAGE_WORDS * 4;
        const uint32_t sW = sA + TILE_WORDS * 4;
#pragma unroll
        for (int i = 0; i < 8; i++) {
            const int c   = tid + i * 128;
            const int row = c >> 3;
            const int c8  = c & 7;
            cp_async16(sA + (uint32_t)(row * SA + c8 * 4) * 4,
                       Ag + (size_t)row * K + k0 + c8 * 4);
        }
#pragma unroll
        for (int i = 0; i < 8; i++) {
            const int c   = tid + i * 128;
            const int row = c >> 3;
            const int c8  = c & 7;
            cp_async16(sW + (uint32_t)(row * SA + c8 * 4) * 4,
                       Wg + (size_t)row * K + k0 + c8 * 4);
        }
        cp_commit();
    };

    float acc[4][8][4];
#pragma unroll
    for (int mt = 0; mt < 4; mt++)
#pragma unroll
        for (int nt = 0; nt < 8; nt++)
#pragma unroll
            for (int i = 0; i < 4; i++)
                acc[mt][nt][i] = 0.0f;

    load_stage(0, 0);
    load_stage(1, KC);

    for (int kt = 0; kt < KT; ++kt) {
        cp_wait<1>();
        __syncthreads();

        const float* Asm = sm + (kt & 1) * STAGE_WORDS;
        const float* Wsm = Asm + TILE_WORDS;
        const float* ap = Asm + (wm * 64 + g) * SA;
        const float* bp = Wsm + (wn * 64 + g) * SA;

#pragma unroll
        for (int ks = 0; ks < KC / 8; ks++) {
            const int k0 = ks * 8 + t;

            uint32_t Bh[16];
#pragma unroll
            for (int nt = 0; nt < 8; nt++) {
                Bh[nt * 2]     = f2tf32(bp[nt * 8 * SA + k0]);
                Bh[nt * 2 + 1] = f2tf32(bp[nt * 8 * SA + k0 + 4]);
            }
            uint32_t Ah[16];
#pragma unroll
            for (int mt = 0; mt < 4; mt++) {
                Ah[mt * 4 + 0] = f2tf32(ap[mt * 16 * SA + k0]);
                Ah[mt * 4 + 1] = f2tf32(ap[mt * 16 * SA + 8 * SA + k0]);
                Ah[mt * 4 + 2] = f2tf32(ap[mt * 16 * SA + k0 + 4]);
                Ah[mt * 4 + 3] = f2tf32(ap[mt * 16 * SA + 8 * SA + k0 + 4]);
            }

#pragma unroll
            for (int mt = 0; mt < 4; mt++)
#pragma unroll
                for (int nt = 0; nt < 8; nt++)
                    mma_tf32(acc[mt][nt], &Ah[mt * 4], &Bh[nt * 2]);
        }

        __syncthreads();
        if (kt + 2 < KT) load_stage(kt & 1, (kt + 2) * KC);
        else cp_commit();
    }

#pragma unroll
    for (int mt = 0; mt < 4; mt++) {
        const int row0 = mBase + wm * 64 + mt * 16 + g;
#pragma unroll
        for (int nt = 0; nt < 8; nt++) {
            const int col = nBase + wn * 64 + nt * 8 + 2 * t;
            float2* p0 = (float2*)(C + (size_t)row0 * E + col);
            float2* p1 = (float2*)(C + (size_t)(row0 + 8) * E + col);
            *p0 = make_float2(acc[mt][nt][0], acc[mt][nt][1]);
            *p1 = make_float2(acc[mt][nt][2], acc[mt][nt][3]);
        }
    }
}

// ---------------- top-8 routing + flagging (vectorized, e = lane*8+j) -------
__global__ __launch_bounds__(256)
void router_topk_kernel(const float* __restrict__ logits,
                        const float* __restrict__ bias,
                        float* __restrict__ probs,
                        float* __restrict__ rmap,
                        int N)
{
    const int warp = (blockIdx.x * blockDim.x + threadIdx.x) >> 5;
    const int lane = threadIdx.x & 31;
    if (warp >= N) return;

    const float* lrow = logits + (size_t)warp * 256;

    float x[8], biasv[8];
    {
        const float4 l0 = *(const float4*)(lrow + lane * 8);
        const float4 l1 = *(const float4*)(lrow + lane * 8 + 4);
        x[0]=l0.x; x[1]=l0.y; x[2]=l0.z; x[3]=l0.w;
        x[4]=l1.x; x[5]=l1.y; x[6]=l1.z; x[7]=l1.w;
        const float4 b0 = *(const float4*)(bias + lane * 8);
        const float4 b1 = *(const float4*)(bias + lane * 8 + 4);
        biasv[0]=b0.x; biasv[1]=b0.y; biasv[2]=b0.z; biasv[3]=b0.w;
        biasv[4]=b1.x; biasv[5]=b1.y; biasv[6]=b1.z; biasv[7]=b1.w;
    }

    float score[8], selsc[8];
    bool  sel[8];
#pragma unroll
    for (int j = 0; j < 8; j++) {
        const float sp = fmaxf(x[j], 0.0f) + log1pf(expf(-fabsf(x[j])));
        score[j] = sqrtf(sp);
        selsc[j] = score[j] + biasv[j];
        sel[j] = false;
    }

    float sumw = 0.0f, v8 = 0.0f, v9 = 0.0f;
#pragma unroll
    for (int it = 0; it < 9; it++) {
        float bestv = -INFINITY;
        int bestj = -1;
#pragma unroll
        for (int j = 0; j < 8; j++)
            if (selsc[j] > bestv) { bestv = selsc[j]; bestj = j; }
        int beste = (bestj >= 0) ? (lane * 8 + bestj) : 0x7fffffff;
        warp_argmax(bestv, beste);
        if (it == 7) v8 = bestv;
        if (it == 8) { v9 = bestv; break; }
        if ((beste >> 3) == lane) {
            const int j = beste & 7;
            sel[j] = true;
            selsc[j] = -INFINITY;
            sumw += score[j];
        }
    }

    float tot = sumw;
#pragma unroll
    for (int off = 16; off > 0; off >>= 1)
        tot += __shfl_xor_sync(0xffffffffu, tot, off);
    const float scale = 2.5f / fmaxf(tot, 1e-12f);

    const size_t orow = (size_t)warp * 256;
    float4 p0, p1, m0, m1;
    p0.x = sel[0] ? score[0]*scale : 0.0f;  m0.x = sel[0] ? 1.0f : 0.0f;
    p0.y = sel[1] ? score[1]*scale : 0.0f;  m0.y = sel[1] ? 1.0f : 0.0f;
    p0.z = sel[2] ? score[2]*scale : 0.0f;  m0.z = sel[2] ? 1.0f : 0.0f;
    p0.w = sel[3] ? score[3]*scale : 0.0f;  m0.w = sel[3] ? 1.0f : 0.0f;
    p1.x = sel[4] ? score[4]*scale : 0.0f;  m1.x = sel[4] ? 1.0f : 0.0f;
    p1.y = sel[5] ? score[5]*scale : 0.0f;  m1.y = sel[5] ? 1.0f : 0.0f;
    p1.z = sel[6] ? score[6]*scale : 0.0f;  m1.z = sel[6] ? 1.0f : 0.0f;
    p1.w = sel[7] ? score[7]*scale : 0.0f;  m1.w = sel[7] ? 1.0f : 0.0f;
    *(float4*)(probs + orow + lane * 8)     = p0;
    *(float4*)(probs + orow + lane * 8 + 4) = p1;
    *(float4*)(rmap  + orow + lane * 8)     = m0;
    *(float4*)(rmap  + orow + lane * 8 + 4) = m1;

    if (lane == 0 && (v8 - v9) < TAU) {
        const int idx = atomicAdd(&g_flag_count, 1);
        g_flag_list[idx] = warp;
    }
}

// ---------------- targeted exact refinement (one block / flagged token) -----
__global__ __launch_bounds__(128)
void refine_kernel(const float* __restrict__ A,
                   const float* __restrict__ W,
                   const float* __restrict__ bias,
                   const float* __restrict__ logits,
                   float* __restrict__ probs,
                   float* __restrict__ rmap,
                   int K)
{
    __shared__ float hsm[4096];
    __shared__ float wbuf[2][RNC][RCK + RPAD];
    __shared__ float exsc[32];
    __shared__ int   exid[32];
    __shared__ int   ncs;

    const int tid  = threadIdx.x;
    const int wid  = tid >> 5;
    const int lane = tid & 31;
    const int cnt  = g_flag_count;
    const int NCH  = K / RCK;          // 4

    for (int i = blockIdx.x; i < cnt; i += gridDim.x) {
        const int tk = g_flag_list[i];

        const float4* hsrc = (const float4*)(A + (size_t)tk * K);
        for (int j = tid; j < K / 4; j += 128)
            ((float4*)hsm)[j] = hsrc[j];

        float score[8], selsc[8], biasv[8];
        if (wid == 0) {
            const float* lrow = logits + (size_t)tk * 256;
#pragma unroll
            for (int j = 0; j < 8; j++) {
                const int e = j * 32 + lane;
                const float x = lrow[e];
                const float sp = fmaxf(x, 0.0f) + log1pf(expf(-fabsf(x)));
                score[j] = sqrtf(sp);
                biasv[j] = bias[e];
                selsc[j] = score[j] + biasv[j];
            }
            float tmp[8];
#pragma unroll
            for (int j = 0; j < 8; j++) tmp[j] = selsc[j];
            float v8 = -INFINITY;
#pragma unroll
            for (int it = 0; it < 8; it++) {
                float bestv = -INFINITY;
                int bestj = -1;
#pragma unroll
                for (int j = 0; j < 8; j++)
                    if (tmp[j] > bestv) { bestv = tmp[j]; bestj = j; }
                int beste = (bestj >= 0) ? (bestj * 32 + lane) : 0x7fffffff;
                warp_argmax(bestv, beste);
                if (it == 7) v8 = bestv;
                if ((beste & 31) == lane) tmp[beste >> 5] = -INFINITY;
            }
            if (lane == 0) ncs = 0;
            __syncwarp();
#pragma unroll
            for (int j = 0; j < 8; j++) {
                if (fabsf(selsc[j] - v8) <= TAU) {
                    const int slot = atomicAdd(&ncs, 1);
                    if (slot < 32) exid[slot] = j * 32 + lane;
                }
            }
        }
        __syncthreads();
        const int nc = min(ncs, 32);

        for (int c0 = 0; c0 < nc; c0 += RNC) {
            const int gnc = min(RNC, nc - c0);

            for (int idx = tid; idx < gnc * (RCK / 4); idx += 128) {
                const int cand = idx / (RCK / 4);
                const int f4   = idx % (RCK / 4);
                const int e    = exid[c0 + cand];
                *(float4*)&wbuf[0][cand][f4 * 4] =
                    *(const float4*)(W + (size_t)e * K + f4 * 4);
            }
            __syncthreads();

            float acc = 0.0f;
            for (int ch = 0; ch < NCH; ch++) {
                const int cur = ch & 1;
                if (wid > 0) {
                    if (ch + 1 < NCH) {
                        const int tj = tid - 32;
                        for (int idx = tj; idx < gnc * (RCK / 4); idx += 96) {
                            const int cand = idx / (RCK / 4);
                            const int f4   = idx % (RCK / 4);
                            const int e    = exid[c0 + cand];
                            *(float4*)&wbuf[cur ^ 1][cand][f4 * 4] =
                                *(const float4*)(W + (size_t)e * K + (ch + 1) * RCK + f4 * 4);
                        }
                    }
                } else if (lane < gnc) {
                    // bit-exact ascending-k single-accumulator fmaf chain
                    const float* wv = wbuf[cur][lane];
                    const float* hv = hsm + ch * RCK;
#pragma unroll 8
                    for (int k = 0; k < RCK; k += 4) {
                        acc = fmaf(hv[k],     wv[k],     acc);
                        acc = fmaf(hv[k + 1], wv[k + 1], acc);
                        acc = fmaf(hv[k + 2], wv[k + 2], acc);
                        acc = fmaf(hv[k + 3], wv[k + 3], acc);
                    }
                }
                __syncthreads();
            }
            if (wid == 0 && lane < gnc) {
                const float sp = fmaxf(acc, 0.0f) + log1pf(expf(-fabsf(acc)));
                exsc[c0 + lane] = sqrtf(sp);
            }
            __syncthreads();
        }

        if (wid == 0) {
            for (int c = 0; c < nc; c++) {
                const int e = exid[c];
                if ((e & 31) == lane) {
                    const int j = e >> 5;
                    score[j] = exsc[c];
                    selsc[j] = score[j] + biasv[j];
                }
            }
            bool sel[8];
#pragma unroll
            for (int j = 0; j < 8; j++) sel[j] = false;
            float sumw = 0.0f;
#pragma unroll
            for (int it = 0; it < 8; it++) {
                float bestv = -INFINITY;
                int bestj = -1;
#pragma unroll
                for (int j = 0; j < 8; j++)
                    if (selsc[j] > bestv) { bestv = selsc[j]; bestj = j; }
                int beste = (bestj >= 0) ? (bestj * 32 + lane) : 0x7fffffff;
                warp_argmax(bestv, beste);
                if ((beste & 31) == lane) {
                    const int j = beste >> 5;
                    sel[j] = true;
                    selsc[j] = -INFINITY;
                    sumw += score[j];
                }
            }
            float tot = sumw;
#pragma unroll
            for (int off = 16; off > 0; off >>= 1)
                tot += __shfl_xor_sync(0xffffffffu, tot, off);
            const float scale = 2.5f / fmaxf(tot, 1e-12f);

#pragma unroll
            for (int j = 0; j < 8; j++) {
                const int e = j * 32 + lane;
                const size_t o = (size_t)tk * 256 + e;
                probs[o] = sel[j] ? score[j] * scale : 0.0f;
                rmap[o]  = sel[j] ? 1.0f : 0.0f;
            }
        }
        __syncthreads();
    }
}

extern "C" void kernel_launch(void* const* d_in, const int* in_sizes, int n_in,
                              void* d_out, int out_size)
{
    const float* hidden = (const float*)d_in[0];
    const float* weight = (const float*)d_in[1];
    const float* bias   = (const float*)d_in[2];

    const int E = in_sizes[2];
    const int D = in_sizes[1] / E;
    const int N = in_sizes[0] / D;

    float* out   = (float*)d_out;
    float* probs = out;
    float* rmap  = out + (size_t)N * E;

    float* logits = nullptr;
    cudaGetSymbolAddress((void**)&logits, g_logits);
    void* fc = nullptr;
    cudaGetSymbolAddress(&fc, g_flag_count);

    cudaMemsetAsync(fc, 0, sizeof(int));

    cudaFuncSetAttribute(gemm_tf32_kernel,
                         cudaFuncAttributeMaxDynamicSharedMemorySize, SMEM_BYTES);

    dim3 grid(E / BN, N / BM);   // (2, 128)
    gemm_tf32_kernel<<<grid, 128, SMEM_BYTES>>>(hidden, weight, logits, E, D);

    router_topk_kernel<<<N / 8, 256>>>(logits, bias, probs, rmap, N);

    refine_kernel<<<2048, 128>>>(hidden, weight, bias, logits, probs, rmap, D);

    (void)n_in; (void)out_size;
}